// round 11
// baseline (speedup 1.0000x reference)
#include <cuda_runtime.h>
#include <cuda_fp16.h>
#include <cstdint>

#define BB 32
#define SS 512
#define DD 1024

// ---- device scratch (module-load allocated; no runtime allocs) ----
// E normalized fp16: [row][k] contiguous (2048B per row)
__device__ unsigned short g_eh[(size_t)BB * SS * DD];       // 32 MB
// aspect parity copies fp16: per batch 16 buffers x 2056 u16 (4112 B):
//   buf (h*8+p), h=0 hi / h=1 lo: buf[x] = a2_h[x + p], x in [0,2048)
//   a2_h[y] = aspect_h[y mod 1024]
__device__ __align__(16) unsigned short g_asp16[BB * 16 * 2056];  // 4.2 MB

// ============================ helpers ============================
__device__ __forceinline__ uint32_t smem_u32(const void* p) {
    uint32_t a;
    asm("{ .reg .u64 t; cvta.to.shared.u64 t, %1; cvt.u32.u64 %0, t; }" : "=r"(a) : "l"(p));
    return a;
}
__device__ __forceinline__ void cpasync16(uint32_t dst, const void* src) {
    asm volatile("cp.async.cg.shared.global [%0], [%1], 16;" :: "r"(dst), "l"(src));
}
__device__ __forceinline__ void ldsm4(uint32_t* r, uint32_t a) {
    asm volatile("ldmatrix.sync.aligned.m8n8.x4.shared.b16 {%0,%1,%2,%3}, [%4];"
                 : "=r"(r[0]), "=r"(r[1]), "=r"(r[2]), "=r"(r[3]) : "r"(a));
}
__device__ __forceinline__ void mma16816(float* c, const uint32_t* a, const uint32_t* b) {
    asm volatile(
        "mma.sync.aligned.m16n8k16.row.col.f32.f16.f16.f32 "
        "{%0,%1,%2,%3}, {%4,%5,%6,%7}, {%8,%9}, {%0,%1,%2,%3};"
        : "+f"(c[0]), "+f"(c[1]), "+f"(c[2]), "+f"(c[3])
        : "r"(a[0]), "r"(a[1]), "r"(a[2]), "r"(a[3]), "r"(b[0]), "r"(b[1]));
}

// ============================ prep kernel (fused) ============================
// blockIdx.x < SS : normalize E row -> fp16
// blockIdx.x == SS: normalize aspect -> 16 parity copies (hi/lo)
__global__ void prep_kernel(const float* __restrict__ e, const float* __restrict__ a) {
    int bx = blockIdx.x, b = blockIdx.y, t = threadIdx.x;  // 256 threads
    const float* src = (bx < SS) ? (e + ((size_t)b * SS + bx) * DD)
                                 : (a + (size_t)b * DD);
    float4 v = ((const float4*)src)[t];
    float sum = v.x * v.x + v.y * v.y + v.z * v.z + v.w * v.w;
    #pragma unroll
    for (int o = 16; o; o >>= 1) sum += __shfl_xor_sync(0xffffffffu, sum, o);
    __shared__ float ws[8];
    __shared__ float s_inv;
    if ((t & 31) == 0) ws[t >> 5] = sum;
    __syncthreads();
    if (t == 0) {
        float tot = 0.f;
        #pragma unroll
        for (int i = 0; i < 8; i++) tot += ws[i];
        s_inv = (tot > 0.f) ? rsqrtf(tot) : 0.f;
    }
    __syncthreads();
    float inv = s_inv;
    float n[4] = {v.x * inv, v.y * inv, v.z * inv, v.w * inv};

    if (bx < SS) {
        ushort4 ph;
        unsigned short* hp = &ph.x;
        #pragma unroll
        for (int j = 0; j < 4; j++)
            hp[j] = __half_as_ushort(__float2half(n[j]));
        ((ushort4*)(g_eh + ((size_t)b * SS + bx) * DD))[t] = ph;
    } else {
        unsigned short* base = g_asp16 + (size_t)b * 16 * 2056;
        #pragma unroll
        for (int j = 0; j < 4; j++) {
            __half h = __float2half(n[j]);
            __half l = __float2half(n[j] - __half2float(h));
            unsigned short hu = __half_as_ushort(h);
            unsigned short lu = __half_as_ushort(l);
            int eidx = 4 * t + j;
            #pragma unroll
            for (int p = 0; p < 8; p++) {
                // buf_p[x] = a2[x+p]: x = eidx - p (+1024), within [0,2048)
                int x0 = eidx - p;
                unsigned short* bh = base + p * 2056;
                unsigned short* bl = base + (8 + p) * 2056;
                if (x0 >= 0) { bh[x0] = hu; bl[x0] = lu; }
                int x1 = x0 + 1024;
                if (x1 < 2048) { bh[x1] = hu; bl[x1] = lu; }
                int x2 = x0 + 2048;           // covers e<p wrap (x0<0 -> x0+1024 handled, x0+2048 not needed)
                (void)x2;
            }
        }
    }
}

// ============================ GEMM kernel ============================
// out[b, s_base+m, i_base+n] = sum_k E[m][k] * Circ[n][k]
// E fp16 (A, cp.async ring), Circ = fp16 hi+lo read DIRECTLY from parity
// aspect copies in smem (no B build, no CTA barrier in mainloop).
// CTA 128x128, 512 thr (16 warps, warp 32x32), k-chunk 64.
// Sync: per-4-warp-group named barriers (group = A 32-row slice).
#define ROWA 144                 // 128B payload + 16B pad
#define ASTG (128 * ROWA)        // 18432 per A stage
#define OFF_ASP (2 * ASTG)       // 36864
#define BUFS 4112                // parity buffer stride (bytes): 4096 + 16 stagger
#define SMEM_DYN (OFF_ASP + 16 * BUFS)   // 102656
#define NCHUNK 16                // 1024 / 64

__global__ void __launch_bounds__(512, 1) gemm_kernel(float* __restrict__ out) {
    extern __shared__ __align__(128) char smem[];
    const uint32_t sbase = smem_u32(smem);
    const uint32_t sAsp = sbase + OFF_ASP;

    const int b      = blockIdx.z;
    const int i_base = blockIdx.x * 128;
    const int s_base = blockIdx.y * 128;
    const int tid  = threadIdx.x;
    const int wid  = tid >> 5;
    const int lane = tid & 31;
    const int g  = wid & 3;      // A-slice group (rows g*32..g*32+31), 4 warps, same SMSP
    const int wn = wid >> 2;     // n-group of 32

    // A loader (within group): 128 threads cover 32 rows x 8 segs, 2 segs each
    const int wgt  = (wid >> 2) * 32 + lane;   // 0..127 within group
    const int rowl = wgt >> 2;                 // 0..31
    const int seg2 = (wgt & 3) * 2;            // 0,2,4,6
    const char* pA = (const char*)g_eh
        + ((size_t)b * SS + s_base + g * 32 + rowl) * 2048 + seg2 * 16;
    const uint32_t drowA = sbase + (uint32_t)(g * 32 + rowl) * ROWA + seg2 * 16;

    // A ldmatrix lane offset
    const uint32_t a_lane = (uint32_t)(g * 32 + (lane & 15)) * ROWA + (lane >> 4) * 16;

    // B direct ldmatrix base addresses (lane-dependent, loop-invariant parity)
    uint32_t bA[2];
    #pragma unroll
    for (int p = 0; p < 2; p++) {
        int nidx = wn * 32 + p * 16 + (lane & 7) + 8 * (lane >> 4);
        int kb   = ((lane >> 3) & 1) * 8;
        int s0   = DD + kb - (i_base + nidx);      // >= 1
        int pp   = s0 & 7;
        bA[p] = sAsp + (uint32_t)pp * BUFS + (uint32_t)((s0 >> 3) << 4);
    }
    const uint32_t LO = 8 * BUFS;                  // hi -> lo buffer offset

    float acc[2][4][4];
    #pragma unroll
    for (int mt = 0; mt < 2; mt++)
        #pragma unroll
        for (int nt = 0; nt < 4; nt++)
            #pragma unroll
            for (int j = 0; j < 4; j++) acc[mt][nt][j] = 0.f;

    #define LOAD_A(ST, KC) do {                                         \
        uint32_t d_ = drowA + (ST) * ASTG;                              \
        const char* s_ = pA + (size_t)(KC) * 128;                       \
        cpasync16(d_, s_);                                              \
        cpasync16(d_ + 16, s_ + 16);                                    \
        asm volatile("cp.async.commit_group;");                         \
    } while (0)

    // ---- prologue: aspect parity copies + A(0), one CTA-wide sync ----
    {
        const char* pAsp = (const char*)g_asp16 + (size_t)b * (16 * BUFS / 16) * 16;
        for (int j = tid; j < 16 * BUFS / 16; j += 512)
            cpasync16(sAsp + j * 16, pAsp + (size_t)j * 16);
    }
    LOAD_A(0, 0);
    asm volatile("cp.async.wait_group 0;" ::: "memory");
    __syncthreads();

    uint32_t bcoff = 0;   // B chunk byte offset (+128 per chunk)
    #pragma unroll 2
    for (int c = 0; c < NCHUNK; c++) {
        if (c + 1 < NCHUNK) LOAD_A((c + 1) & 1, c + 1);

        const uint32_t sa = sbase + (c & 1) * ASTG;

        #pragma unroll
        for (int kk = 0; kk < 4; kk++) {
            const uint32_t akb = (uint32_t)(kk * 32);   // A: 16 k per step
            const uint32_t bkk = bcoff + (uint32_t)(kk * 32);
            uint32_t aH[2][4], bH[2][4], bL[2][4];
            #pragma unroll
            for (int mt = 0; mt < 2; mt++)
                ldsm4(aH[mt], sa + a_lane + mt * 16 * ROWA + akb);
            #pragma unroll
            for (int p = 0; p < 2; p++)
                ldsm4(bH[p], bA[p] + bkk);
            #pragma unroll
            for (int p = 0; p < 2; p++)
                ldsm4(bL[p], bA[p] + LO + bkk);
            #pragma unroll
            for (int mt = 0; mt < 2; mt++)
                #pragma unroll
                for (int nt = 0; nt < 4; nt++)
                    mma16816(acc[mt][nt], aH[mt], &bH[nt >> 1][2 * (nt & 1)]);
            #pragma unroll
            for (int mt = 0; mt < 2; mt++)
                #pragma unroll
                for (int nt = 0; nt < 4; nt++)
                    mma16816(acc[mt][nt], aH[mt], &bL[nt >> 1][2 * (nt & 1)]);
        }
        bcoff += 128;

        if (c + 1 < NCHUNK) {
            asm volatile("cp.async.wait_group 0;" ::: "memory");
            asm volatile("bar.sync %0, %1;" :: "r"(g + 1), "r"(128) : "memory");
        }
    }

    // ---- epilogue: direct f32 stores ----
    #pragma unroll
    for (int mt = 0; mt < 2; mt++) {
        int rr = s_base + g * 32 + mt * 16 + (lane >> 2);
        float* p0 = out + ((size_t)b * SS + rr) * DD + i_base + wn * 32 + (lane & 3) * 2;
        float* p1 = p0 + (size_t)8 * DD;
        #pragma unroll
        for (int nt = 0; nt < 4; nt++) {
            *(float2*)(p0 + nt * 8) = make_float2(acc[mt][nt][0], acc[mt][nt][1]);
            *(float2*)(p1 + nt * 8) = make_float2(acc[mt][nt][2], acc[mt][nt][3]);
        }
    }
}

// ============================ launch ============================
extern "C" void kernel_launch(void* const* d_in, const int* in_sizes, int n_in,
                              void* d_out, int out_size) {
    const float* emb = (const float*)d_in[0];   // (32, 512, 1024) f32
    const float* asp = (const float*)d_in[1];   // (32, 1024) f32
    float* out = (float*)d_out;                 // (32, 512, 1024) f32

    cudaFuncSetAttribute(gemm_kernel, cudaFuncAttributeMaxDynamicSharedMemorySize, SMEM_DYN);

    prep_kernel<<<dim3(SS + 1, BB), 256>>>(emb, asp);
    gemm_kernel<<<dim3(DD / 128, SS / 128, BB), 512, SMEM_DYN>>>(out);
}

// round 12
// speedup vs baseline: 1.0843x; 1.0843x over previous
#include <cuda_runtime.h>
#include <cuda_fp16.h>
#include <cstdint>

#define BB 32
#define SS 512
#define DD 1024

// ---- device scratch (module-load allocated; no runtime allocs) ----
// E normalized fp16: [row][k] contiguous (2048B per row)
__device__ unsigned short g_eh[(size_t)BB * SS * DD];       // 32 MB
// aspect parity copies fp16: per batch 16 buffers x 2056 u16 (4112 B):
//   buf (h*8+p), h=0 hi / h=1 lo: buf[x] = a2_h[x + p], x in [0,2048)
__device__ __align__(16) unsigned short g_asp16[BB * 16 * 2056];  // 4.2 MB

// ============================ helpers ============================
__device__ __forceinline__ uint32_t smem_u32(const void* p) {
    uint32_t a;
    asm("{ .reg .u64 t; cvta.to.shared.u64 t, %1; cvt.u32.u64 %0, t; }" : "=r"(a) : "l"(p));
    return a;
}
__device__ __forceinline__ void cpasync16(uint32_t dst, const void* src) {
    asm volatile("cp.async.cg.shared.global [%0], [%1], 16;" :: "r"(dst), "l"(src));
}
__device__ __forceinline__ void ldsm4(uint32_t* r, uint32_t a) {
    asm volatile("ldmatrix.sync.aligned.m8n8.x4.shared.b16 {%0,%1,%2,%3}, [%4];"
                 : "=r"(r[0]), "=r"(r[1]), "=r"(r[2]), "=r"(r[3]) : "r"(a));
}
__device__ __forceinline__ void mma16816(float* c, const uint32_t* a, const uint32_t* b) {
    asm volatile(
        "mma.sync.aligned.m16n8k16.row.col.f32.f16.f16.f32 "
        "{%0,%1,%2,%3}, {%4,%5,%6,%7}, {%8,%9}, {%0,%1,%2,%3};"
        : "+f"(c[0]), "+f"(c[1]), "+f"(c[2]), "+f"(c[3])
        : "r"(a[0]), "r"(a[1]), "r"(a[2]), "r"(a[3]), "r"(b[0]), "r"(b[1]));
}

// ============================ prep kernel (fused) ============================
__global__ void prep_kernel(const float* __restrict__ e, const float* __restrict__ a) {
    int bx = blockIdx.x, b = blockIdx.y, t = threadIdx.x;  // 256 threads
    const float* src = (bx < SS) ? (e + ((size_t)b * SS + bx) * DD)
                                 : (a + (size_t)b * DD);
    float4 v = ((const float4*)src)[t];
    float sum = v.x * v.x + v.y * v.y + v.z * v.z + v.w * v.w;
    #pragma unroll
    for (int o = 16; o; o >>= 1) sum += __shfl_xor_sync(0xffffffffu, sum, o);
    __shared__ float ws[8];
    __shared__ float s_inv;
    if ((t & 31) == 0) ws[t >> 5] = sum;
    __syncthreads();
    if (t == 0) {
        float tot = 0.f;
        #pragma unroll
        for (int i = 0; i < 8; i++) tot += ws[i];
        s_inv = (tot > 0.f) ? rsqrtf(tot) : 0.f;
    }
    __syncthreads();
    float inv = s_inv;
    float n[4] = {v.x * inv, v.y * inv, v.z * inv, v.w * inv};

    if (bx < SS) {
        ushort4 ph;
        unsigned short* hp = &ph.x;
        #pragma unroll
        for (int j = 0; j < 4; j++)
            hp[j] = __half_as_ushort(__float2half(n[j]));
        ((ushort4*)(g_eh + ((size_t)b * SS + bx) * DD))[t] = ph;
    } else {
        unsigned short* base = g_asp16 + (size_t)b * 16 * 2056;
        #pragma unroll
        for (int j = 0; j < 4; j++) {
            __half h = __float2half(n[j]);
            __half l = __float2half(n[j] - __half2float(h));
            unsigned short hu = __half_as_ushort(h);
            unsigned short lu = __half_as_ushort(l);
            int eidx = 4 * t + j;
            #pragma unroll
            for (int p = 0; p < 8; p++) {
                int x0 = eidx - p;
                unsigned short* bh = base + p * 2056;
                unsigned short* bl = base + (8 + p) * 2056;
                if (x0 >= 0) { bh[x0] = hu; bl[x0] = lu; }
                int x1 = x0 + 1024;
                if (x1 < 2048) { bh[x1] = hu; bl[x1] = lu; }
            }
        }
    }
}

// ============================ GEMM kernel ============================
// out[b, s_base+m, i_base+n] = sum_k E[m][k] * Circ[n][k]
// E fp16 (A ring), Circ fp16 hi+lo ldsm'd DIRECTLY from parity aspect copies.
// CTA 128x128, 256 thr (8 warps, warp 64x32), k-chunk 64, 2 CTAs/SM.
#define ROWA 144                 // 128B payload + 16B pad
#define ASTG (128 * ROWA)        // 18432 per A stage
#define OFF_ASP (2 * ASTG)       // 36864
#define BUFS 4112                // parity buffer stride (bytes)
#define SMEM_DYN (OFF_ASP + 16 * BUFS)   // 102656
#define NCHUNK 16                // 1024 / 64

__global__ void __launch_bounds__(256, 2) gemm_kernel(float* __restrict__ out) {
    extern __shared__ __align__(128) char smem[];
    const uint32_t sbase = smem_u32(smem);
    const uint32_t sAsp = sbase + OFF_ASP;

    const int b      = blockIdx.z;
    const int i_base = blockIdx.x * 128;
    const int s_base = blockIdx.y * 128;
    const int tid  = threadIdx.x;
    const int wid  = tid >> 5;
    const int lane = tid & 31;
    const int wm = wid & 1;      // 2 m-groups of 64
    const int wn = wid >> 1;     // 4 n-groups of 32

    // A loader: thread covers row tid>>1, 64B half (tid&1): 4 x 16B
    const int r0 = tid >> 1;
    const int h64 = (tid & 1) * 64;
    const char* pA = (const char*)g_eh + ((size_t)b * SS + s_base + r0) * 2048 + h64;
    const uint32_t drowA = sbase + (uint32_t)r0 * ROWA + h64;

    // A ldmatrix lane offset
    const uint32_t a_lane = (uint32_t)(wm * 64 + (lane & 15)) * ROWA + (lane >> 4) * 16;

    // B direct ldmatrix base addresses (lane-dependent, loop-invariant parity)
    uint32_t bA[2];
    #pragma unroll
    for (int p = 0; p < 2; p++) {
        int nidx = wn * 32 + p * 16 + (lane & 7) + 8 * (lane >> 4);
        int kb   = ((lane >> 3) & 1) * 8;
        int s0   = DD + kb - (i_base + nidx);      // >= 1
        int pp   = s0 & 7;
        bA[p] = sAsp + (uint32_t)pp * BUFS + (uint32_t)((s0 >> 3) << 4);
    }
    const uint32_t LO = 8 * BUFS;                  // hi -> lo buffer offset

    float acc[4][4][4];
    #pragma unroll
    for (int mt = 0; mt < 4; mt++)
        #pragma unroll
        for (int nt = 0; nt < 4; nt++)
            #pragma unroll
            for (int j = 0; j < 4; j++) acc[mt][nt][j] = 0.f;

    #define LOAD_A(ST, KC) do {                                         \
        uint32_t d_ = drowA + (ST) * ASTG;                              \
        const char* s_ = pA + (size_t)(KC) * 128;                       \
        cpasync16(d_,      s_);                                         \
        cpasync16(d_ + 16, s_ + 16);                                    \
        cpasync16(d_ + 32, s_ + 32);                                    \
        cpasync16(d_ + 48, s_ + 48);                                    \
        asm volatile("cp.async.commit_group;");                         \
    } while (0)

    // ---- prologue: aspect parity copies + A(0) ----
    {
        const char* pAsp = (const char*)g_asp16 + (size_t)b * 16 * BUFS;
        for (int j = tid; j < 16 * BUFS / 16; j += 256)
            cpasync16(sAsp + j * 16, pAsp + (size_t)j * 16);
    }
    LOAD_A(0, 0);
    asm volatile("cp.async.wait_group 0;" ::: "memory");
    __syncthreads();

    uint32_t bcoff = 0;   // B chunk byte offset (+128 per chunk)
    #pragma unroll 2
    for (int c = 0; c < NCHUNK; c++) {
        if (c + 1 < NCHUNK) LOAD_A((c + 1) & 1, c + 1);

        const uint32_t sa = sbase + (c & 1) * ASTG;

        #pragma unroll
        for (int kk = 0; kk < 4; kk++) {
            const uint32_t akb = (uint32_t)(kk * 32);
            const uint32_t bkk = bcoff + (uint32_t)(kk * 32);
            uint32_t aH[4][4], bH[2][4], bL[2][4];
            #pragma unroll
            for (int mt = 0; mt < 4; mt++)
                ldsm4(aH[mt], sa + a_lane + mt * 16 * ROWA + akb);
            #pragma unroll
            for (int p = 0; p < 2; p++)
                ldsm4(bH[p], bA[p] + bkk);
            #pragma unroll
            for (int p = 0; p < 2; p++)
                ldsm4(bL[p], bA[p] + LO + bkk);
            #pragma unroll
            for (int mt = 0; mt < 4; mt++)
                #pragma unroll
                for (int nt = 0; nt < 4; nt++)
                    mma16816(acc[mt][nt], aH[mt], &bH[nt >> 1][2 * (nt & 1)]);
            #pragma unroll
            for (int mt = 0; mt < 4; mt++)
                #pragma unroll
                for (int nt = 0; nt < 4; nt++)
                    mma16816(acc[mt][nt], aH[mt], &bL[nt >> 1][2 * (nt & 1)]);
        }
        bcoff += 128;

        if (c + 1 < NCHUNK) {
            asm volatile("cp.async.wait_group 0;" ::: "memory");
            __syncthreads();
        }
    }

    // ---- epilogue: direct f32 stores ----
    #pragma unroll
    for (int mt = 0; mt < 4; mt++) {
        int rr = s_base + wm * 64 + mt * 16 + (lane >> 2);
        float* p0 = out + ((size_t)b * SS + rr) * DD + i_base + wn * 32 + (lane & 3) * 2;
        float* p1 = p0 + (size_t)8 * DD;
        #pragma unroll
        for (int nt = 0; nt < 4; nt++) {
            *(float2*)(p0 + nt * 8) = make_float2(acc[mt][nt][0], acc[mt][nt][1]);
            *(float2*)(p1 + nt * 8) = make_float2(acc[mt][nt][2], acc[mt][nt][3]);
        }
    }
}

// ============================ launch ============================
extern "C" void kernel_launch(void* const* d_in, const int* in_sizes, int n_in,
                              void* d_out, int out_size) {
    const float* emb = (const float*)d_in[0];   // (32, 512, 1024) f32
    const float* asp = (const float*)d_in[1];   // (32, 1024) f32
    float* out = (float*)d_out;                 // (32, 512, 1024) f32

    cudaFuncSetAttribute(gemm_kernel, cudaFuncAttributeMaxDynamicSharedMemorySize, SMEM_DYN);

    prep_kernel<<<dim3(SS + 1, BB), 256>>>(emb, asp);
    gemm_kernel<<<dim3(DD / 128, SS / 128, BB), 256, SMEM_DYN>>>(out);
}